// round 1
// baseline (speedup 1.0000x reference)
#include <cuda_runtime.h>
#include <math.h>

#define BATCH   2
#define SEQ     4096
#define DMODEL  512
#define NHEADS  8
#define DK      64
#define DFF     2048
#define ROWS    (BATCH * SEQ)   // 8192
#define EPS     1e-5f

// ---------------- scratch (static device globals; no allocs allowed) ----------
__device__ float g_Q  [ROWS * DMODEL];   // Q proj; later reused for attn-proj output
__device__ float g_K  [ROWS * DMODEL];   // K proj; later reused for FFN2 output
__device__ float g_V  [ROWS * DMODEL];
__device__ float g_AO [ROWS * DMODEL];   // attention output (concat heads)
__device__ float g_X1 [ROWS * DMODEL];   // post-LN1
__device__ float g_FFH[ROWS * DFF];      // FFN hidden (relu)

// ---------------- generic tiled SGEMM: C = A(MxK) @ B(KxN) + bias, opt relu ----
#define GBM 64
#define GBN 64
#define GBK 16

__global__ void __launch_bounds__(256)
gemm_bias_kernel(const float* __restrict__ A, const float* __restrict__ B,
                 const float* __restrict__ bias, float* __restrict__ C,
                 int M, int N, int K, int relu)
{
    __shared__ float As[GBK][GBM];
    __shared__ float Bs[GBK][GBN];

    const int tid = threadIdx.x;
    const int tx = tid & 15, ty = tid >> 4;
    const int tm = ty * 4, tn = tx * 4;
    const int row0 = blockIdx.y * GBM;
    const int col0 = blockIdx.x * GBN;

    float c[4][4] = {};

    for (int k0 = 0; k0 < K; k0 += GBK) {
        // load A tile transposed: As[k][m]
        #pragma unroll
        for (int i = 0; i < 4; i++) {
            int l  = tid + i * 256;          // 0..1023  (GBM*GBK)
            int m  = l >> 4;
            int kk = l & 15;
            As[kk][m] = A[(row0 + m) * K + k0 + kk];
        }
        // load B tile: Bs[k][n] (fully coalesced)
        #pragma unroll
        for (int i = 0; i < 4; i++) {
            int l  = tid + i * 256;          // 0..1023  (GBK*GBN)
            int kk = l >> 6;
            int n  = l & 63;
            Bs[kk][n] = B[(k0 + kk) * N + col0 + n];
        }
        __syncthreads();

        #pragma unroll
        for (int kk = 0; kk < GBK; kk++) {
            float a[4], b[4];
            #pragma unroll
            for (int i = 0; i < 4; i++) { a[i] = As[kk][tm + i]; b[i] = Bs[kk][tn + i]; }
            #pragma unroll
            for (int i = 0; i < 4; i++)
                #pragma unroll
                for (int j = 0; j < 4; j++)
                    c[i][j] += a[i] * b[j];
        }
        __syncthreads();
    }

    #pragma unroll
    for (int i = 0; i < 4; i++) {
        #pragma unroll
        for (int j = 0; j < 4; j++) {
            float v = c[i][j] + bias[col0 + tn + j];
            if (relu) v = fmaxf(v, 0.0f);
            C[(row0 + tm + i) * N + col0 + tn + j] = v;
        }
    }
}

// ---------------- flash attention (fp32, online softmax) ----------------------
// grid: (SEQ/64, BATCH*NHEADS); block: 256 threads; dyn smem = 4*64*68*4 bytes
#define APAD 68
#define ATT_SMEM (4 * 64 * APAD * (int)sizeof(float))

__global__ void __launch_bounds__(256)
attn_kernel(const float* __restrict__ Q, const float* __restrict__ K,
            const float* __restrict__ V, float* __restrict__ O)
{
    extern __shared__ float sh[];
    float* Qs = sh;                 // [DK][APAD]  d-major, scaled by 1/sqrt(dk)
    float* Ks = Qs + DK * APAD;     // [DK][APAD]  d-major
    float* Vs = Ks + DK * APAD;     // [64][APAD]  n-major
    float* Ps = Vs + 64 * APAD;     // [64][APAD]  n-major (P transposed)

    const int tid = threadIdx.x;
    const int tx = tid & 15, ty = tid >> 4;
    const int tm = ty * 4, tn = tx * 4;

    const int qt = blockIdx.x;
    const int bh = blockIdx.y;
    const int b  = bh >> 3, h = bh & 7;
    const int base = b * SEQ;
    const int q0   = base + qt * 64;
    const int colh = h * DK;

    // load Q tile (transposed, pre-scaled)
    for (int i = tid; i < 64 * DK; i += 256) {
        int m = i >> 6, d = i & 63;
        Qs[d * APAD + m] = 0.125f * Q[(q0 + m) * DMODEL + colh + d];
    }

    float o[4][4] = {};
    float rmax[4], rsum[4];
    #pragma unroll
    for (int i = 0; i < 4; i++) { rmax[i] = -1e30f; rsum[i] = 0.0f; }

    for (int j0 = 0; j0 < SEQ; j0 += 64) {
        __syncthreads();                 // prev iter's reads of Ks/Vs/Ps done
        const int kr = base + j0;
        for (int i = tid; i < 64 * DK; i += 256) {
            int n = i >> 6, d = i & 63;
            Ks[d * APAD + n] = K[(kr + n) * DMODEL + colh + d];
            Vs[n * APAD + d] = V[(kr + n) * DMODEL + colh + d];
        }
        __syncthreads();

        // scores: s[m][n] = sum_d Qs[d][m]*Ks[d][n]   (already scaled)
        float s[4][4] = {};
        #pragma unroll 4
        for (int d = 0; d < DK; d++) {
            float a[4], bb[4];
            #pragma unroll
            for (int i = 0; i < 4; i++) { a[i] = Qs[d * APAD + tm + i]; bb[i] = Ks[d * APAD + tn + i]; }
            #pragma unroll
            for (int i = 0; i < 4; i++)
                #pragma unroll
                for (int j = 0; j < 4; j++)
                    s[i][j] += a[i] * bb[j];
        }

        // online softmax per row (16 lanes per row group compute identical stats)
        #pragma unroll
        for (int i = 0; i < 4; i++) {
            float mx = fmaxf(fmaxf(s[i][0], s[i][1]), fmaxf(s[i][2], s[i][3]));
            #pragma unroll
            for (int off = 8; off; off >>= 1)
                mx = fmaxf(mx, __shfl_xor_sync(0xffffffffu, mx, off));
            float nm   = fmaxf(rmax[i], mx);
            float corr = __expf(rmax[i] - nm);
            rmax[i] = nm;
            float ps = 0.0f;
            #pragma unroll
            for (int j = 0; j < 4; j++) { s[i][j] = __expf(s[i][j] - nm); ps += s[i][j]; }
            #pragma unroll
            for (int off = 8; off; off >>= 1)
                ps += __shfl_xor_sync(0xffffffffu, ps, off);
            rsum[i] = rsum[i] * corr + ps;
            #pragma unroll
            for (int j = 0; j < 4; j++) o[i][j] *= corr;
        }

        // write P transposed: Ps[n][m]
        #pragma unroll
        for (int i = 0; i < 4; i++)
            #pragma unroll
            for (int j = 0; j < 4; j++)
                Ps[(tn + j) * APAD + tm + i] = s[i][j];
        __syncthreads();

        // o[m][d] += sum_n Ps[n][m] * Vs[n][d]
        #pragma unroll 4
        for (int n = 0; n < 64; n++) {
            float p[4], v[4];
            #pragma unroll
            for (int i = 0; i < 4; i++) { p[i] = Ps[n * APAD + tm + i]; v[i] = Vs[n * APAD + tn + i]; }
            #pragma unroll
            for (int i = 0; i < 4; i++)
                #pragma unroll
                for (int j = 0; j < 4; j++)
                    o[i][j] += p[i] * v[j];
        }
    }

    #pragma unroll
    for (int i = 0; i < 4; i++) {
        float inv = 1.0f / rsum[i];
        #pragma unroll
        for (int j = 0; j < 4; j++)
            O[(q0 + tm + i) * DMODEL + colh + tn + j] = o[i][j] * inv;
    }
}

// ---------------- residual add + layernorm (reference form: /(std+eps)) -------
__global__ void __launch_bounds__(128)
add_ln_kernel(const float* __restrict__ A, const float* __restrict__ Bv,
              const float* __restrict__ gamma, const float* __restrict__ beta,
              float* __restrict__ out)
{
    const int row = blockIdx.x;
    const int tid = threadIdx.x;
    __shared__ float red[4];

    const float4 a4 = reinterpret_cast<const float4*>(A  + (size_t)row * DMODEL)[tid];
    const float4 b4 = reinterpret_cast<const float4*>(Bv + (size_t)row * DMODEL)[tid];
    float x0 = a4.x + b4.x, x1 = a4.y + b4.y, x2 = a4.z + b4.z, x3 = a4.w + b4.w;

    float s = x0 + x1 + x2 + x3;
    #pragma unroll
    for (int off = 16; off; off >>= 1) s += __shfl_xor_sync(0xffffffffu, s, off);
    if ((tid & 31) == 0) red[tid >> 5] = s;
    __syncthreads();
    s = red[0] + red[1] + red[2] + red[3];
    const float mean = s * (1.0f / DMODEL);

    float d0 = x0 - mean, d1 = x1 - mean, d2 = x2 - mean, d3 = x3 - mean;
    float v = d0 * d0 + d1 * d1 + d2 * d2 + d3 * d3;
    #pragma unroll
    for (int off = 16; off; off >>= 1) v += __shfl_xor_sync(0xffffffffu, v, off);
    __syncthreads();                       // protect red[] reuse
    if ((tid & 31) == 0) red[tid >> 5] = v;
    __syncthreads();
    v = (red[0] + red[1] + red[2] + red[3]) * (1.0f / DMODEL);

    const float inv = 1.0f / (sqrtf(v) + EPS);
    const float4 g4  = reinterpret_cast<const float4*>(gamma)[tid];
    const float4 be4 = reinterpret_cast<const float4*>(beta )[tid];
    float4 o4;
    o4.x = d0 * inv * g4.x + be4.x;
    o4.y = d1 * inv * g4.y + be4.y;
    o4.z = d2 * inv * g4.z + be4.z;
    o4.w = d3 * inv * g4.w + be4.w;
    reinterpret_cast<float4*>(out + (size_t)row * DMODEL)[tid] = o4;
}

// ---------------- host launch --------------------------------------------------
extern "C" void kernel_launch(void* const* d_in, const int* in_sizes, int n_in,
                              void* d_out, int out_size)
{
    const float* x   = (const float*)d_in[0];
    const float* Wq  = (const float*)d_in[1];
    const float* bq  = (const float*)d_in[2];
    const float* Wk  = (const float*)d_in[3];
    const float* bk  = (const float*)d_in[4];
    const float* Wv  = (const float*)d_in[5];
    const float* bv  = (const float*)d_in[6];
    const float* Wo  = (const float*)d_in[7];
    const float* bo  = (const float*)d_in[8];
    const float* W1  = (const float*)d_in[9];
    const float* b1  = (const float*)d_in[10];
    const float* W2  = (const float*)d_in[11];
    const float* b2  = (const float*)d_in[12];
    const float* g1  = (const float*)d_in[13];
    const float* be1 = (const float*)d_in[14];
    const float* g2  = (const float*)d_in[15];
    const float* be2 = (const float*)d_in[16];
    float* out = (float*)d_out;

    float *Qp, *Kp, *Vp, *AOp, *X1p, *FFHp;
    cudaGetSymbolAddress((void**)&Qp,   g_Q);
    cudaGetSymbolAddress((void**)&Kp,   g_K);
    cudaGetSymbolAddress((void**)&Vp,   g_V);
    cudaGetSymbolAddress((void**)&AOp,  g_AO);
    cudaGetSymbolAddress((void**)&X1p,  g_X1);
    cudaGetSymbolAddress((void**)&FFHp, g_FFH);

    cudaFuncSetAttribute(attn_kernel, cudaFuncAttributeMaxDynamicSharedMemorySize, ATT_SMEM);

    const dim3 t256(256);
    const dim3 gProj(DMODEL / GBN, ROWS / GBM);   // (8, 128)
    const dim3 gFF1 (DFF    / GBN, ROWS / GBM);   // (32, 128)

    // QKV projections
    gemm_bias_kernel<<<gProj, t256>>>(x, Wq, bq, Qp, ROWS, DMODEL, DMODEL, 0);
    gemm_bias_kernel<<<gProj, t256>>>(x, Wk, bk, Kp, ROWS, DMODEL, DMODEL, 0);
    gemm_bias_kernel<<<gProj, t256>>>(x, Wv, bv, Vp, ROWS, DMODEL, DMODEL, 0);

    // attention (flash, per batch-head)
    attn_kernel<<<dim3(SEQ / 64, BATCH * NHEADS), t256, ATT_SMEM>>>(Qp, Kp, Vp, AOp);

    // output projection (into Qp, now free) + LN1
    gemm_bias_kernel<<<gProj, t256>>>(AOp, Wo, bo, Qp, ROWS, DMODEL, DMODEL, 0);
    add_ln_kernel<<<ROWS, 128>>>(x, Qp, g1, be1, X1p);

    // FFN
    gemm_bias_kernel<<<gFF1,  t256>>>(X1p,  W1, b1, FFHp, ROWS, DFF,    DMODEL, 1);
    gemm_bias_kernel<<<gProj, t256>>>(FFHp, W2, b2, Kp,   ROWS, DMODEL, DFF,    0);

    // LN2 -> final output
    add_ln_kernel<<<ROWS, 128>>>(X1p, Kp, g2, be2, out);
}

// round 2
// speedup vs baseline: 1.0005x; 1.0005x over previous
#include <cuda_runtime.h>
#include <math.h>

#define BATCH   2
#define SEQ     4096
#define DMODEL  512
#define NHEADS  8
#define DK      64
#define DFF     2048
#define ROWS    (BATCH * SEQ)   // 8192
#define EPS     1e-5f

// ---------------- scratch (static device globals; no allocs allowed) ----------
__device__ float g_Q  [ROWS * DMODEL];   // Q proj; later reused for attn-proj output
__device__ float g_K  [ROWS * DMODEL];   // K proj; later reused for FFN2 output
__device__ float g_V  [ROWS * DMODEL];
__device__ float g_AO [ROWS * DMODEL];   // attention output (concat heads)
__device__ float g_X1 [ROWS * DMODEL];   // post-LN1
__device__ float g_FFH[ROWS * DFF];      // FFN hidden (relu)

// ---------------- generic tiled SGEMM: C = A(MxK) @ B(KxN) + bias, opt relu ----
#define GBM 64
#define GBN 64
#define GBK 16

__global__ void __launch_bounds__(256)
gemm_bias_kernel(const float* __restrict__ A, const float* __restrict__ B,
                 const float* __restrict__ bias, float* __restrict__ C,
                 int M, int N, int K, int relu)
{
    __shared__ float As[GBK][GBM];
    __shared__ float Bs[GBK][GBN];

    const int tid = threadIdx.x;
    const int tx = tid & 15, ty = tid >> 4;
    const int tm = ty * 4, tn = tx * 4;
    const int row0 = blockIdx.y * GBM;
    const int col0 = blockIdx.x * GBN;

    float c[4][4] = {};

    for (int k0 = 0; k0 < K; k0 += GBK) {
        // load A tile transposed: As[k][m]
        #pragma unroll
        for (int i = 0; i < 4; i++) {
            int l  = tid + i * 256;          // 0..1023  (GBM*GBK)
            int m  = l >> 4;
            int kk = l & 15;
            As[kk][m] = A[(row0 + m) * K + k0 + kk];
        }
        // load B tile: Bs[k][n] (fully coalesced)
        #pragma unroll
        for (int i = 0; i < 4; i++) {
            int l  = tid + i * 256;          // 0..1023  (GBK*GBN)
            int kk = l >> 6;
            int n  = l & 63;
            Bs[kk][n] = B[(k0 + kk) * N + col0 + n];
        }
        __syncthreads();

        #pragma unroll
        for (int kk = 0; kk < GBK; kk++) {
            float a[4], b[4];
            #pragma unroll
            for (int i = 0; i < 4; i++) { a[i] = As[kk][tm + i]; b[i] = Bs[kk][tn + i]; }
            #pragma unroll
            for (int i = 0; i < 4; i++)
                #pragma unroll
                for (int j = 0; j < 4; j++)
                    c[i][j] += a[i] * b[j];
        }
        __syncthreads();
    }

    #pragma unroll
    for (int i = 0; i < 4; i++) {
        #pragma unroll
        for (int j = 0; j < 4; j++) {
            float v = c[i][j] + bias[col0 + tn + j];
            if (relu) v = fmaxf(v, 0.0f);
            C[(row0 + tm + i) * N + col0 + tn + j] = v;
        }
    }
}

// ---------------- flash attention (fp32, online softmax) ----------------------
// grid: (SEQ/64, BATCH*NHEADS); block: 256 threads; dyn smem = 4*64*68*4 bytes
#define APAD 68
#define ATT_SMEM (4 * 64 * APAD * (int)sizeof(float))

__global__ void __launch_bounds__(256)
attn_kernel(const float* __restrict__ Q, const float* __restrict__ K,
            const float* __restrict__ V, float* __restrict__ O)
{
    extern __shared__ float sh[];
    float* Qs = sh;                 // [DK][APAD]  d-major, scaled by 1/sqrt(dk)
    float* Ks = Qs + DK * APAD;     // [DK][APAD]  d-major
    float* Vs = Ks + DK * APAD;     // [64][APAD]  n-major
    float* Ps = Vs + 64 * APAD;     // [64][APAD]  n-major (P transposed)

    const int tid = threadIdx.x;
    const int tx = tid & 15, ty = tid >> 4;
    const int tm = ty * 4, tn = tx * 4;

    const int qt = blockIdx.x;
    const int bh = blockIdx.y;
    const int b  = bh >> 3, h = bh & 7;
    const int base = b * SEQ;
    const int q0   = base + qt * 64;
    const int colh = h * DK;

    // load Q tile (transposed, pre-scaled)
    for (int i = tid; i < 64 * DK; i += 256) {
        int m = i >> 6, d = i & 63;
        Qs[d * APAD + m] = 0.125f * Q[(q0 + m) * DMODEL + colh + d];
    }

    float o[4][4] = {};
    float rmax[4], rsum[4];
    #pragma unroll
    for (int i = 0; i < 4; i++) { rmax[i] = -1e30f; rsum[i] = 0.0f; }

    for (int j0 = 0; j0 < SEQ; j0 += 64) {
        __syncthreads();                 // prev iter's reads of Ks/Vs/Ps done
        const int kr = base + j0;
        for (int i = tid; i < 64 * DK; i += 256) {
            int n = i >> 6, d = i & 63;
            Ks[d * APAD + n] = K[(kr + n) * DMODEL + colh + d];
            Vs[n * APAD + d] = V[(kr + n) * DMODEL + colh + d];
        }
        __syncthreads();

        // scores: s[m][n] = sum_d Qs[d][m]*Ks[d][n]   (already scaled)
        float s[4][4] = {};
        #pragma unroll 4
        for (int d = 0; d < DK; d++) {
            float a[4], bb[4];
            #pragma unroll
            for (int i = 0; i < 4; i++) { a[i] = Qs[d * APAD + tm + i]; bb[i] = Ks[d * APAD + tn + i]; }
            #pragma unroll
            for (int i = 0; i < 4; i++)
                #pragma unroll
                for (int j = 0; j < 4; j++)
                    s[i][j] += a[i] * bb[j];
        }

        // online softmax per row (16 lanes per row group compute identical stats)
        #pragma unroll
        for (int i = 0; i < 4; i++) {
            float mx = fmaxf(fmaxf(s[i][0], s[i][1]), fmaxf(s[i][2], s[i][3]));
            #pragma unroll
            for (int off = 8; off; off >>= 1)
                mx = fmaxf(mx, __shfl_xor_sync(0xffffffffu, mx, off));
            float nm   = fmaxf(rmax[i], mx);
            float corr = __expf(rmax[i] - nm);
            rmax[i] = nm;
            float ps = 0.0f;
            #pragma unroll
            for (int j = 0; j < 4; j++) { s[i][j] = __expf(s[i][j] - nm); ps += s[i][j]; }
            #pragma unroll
            for (int off = 8; off; off >>= 1)
                ps += __shfl_xor_sync(0xffffffffu, ps, off);
            rsum[i] = rsum[i] * corr + ps;
            #pragma unroll
            for (int j = 0; j < 4; j++) o[i][j] *= corr;
        }

        // write P transposed: Ps[n][m]
        #pragma unroll
        for (int i = 0; i < 4; i++)
            #pragma unroll
            for (int j = 0; j < 4; j++)
                Ps[(tn + j) * APAD + tm + i] = s[i][j];
        __syncthreads();

        // o[m][d] += sum_n Ps[n][m] * Vs[n][d]
        #pragma unroll 4
        for (int n = 0; n < 64; n++) {
            float p[4], v[4];
            #pragma unroll
            for (int i = 0; i < 4; i++) { p[i] = Ps[n * APAD + tm + i]; v[i] = Vs[n * APAD + tn + i]; }
            #pragma unroll
            for (int i = 0; i < 4; i++)
                #pragma unroll
                for (int j = 0; j < 4; j++)
                    o[i][j] += p[i] * v[j];
        }
    }

    #pragma unroll
    for (int i = 0; i < 4; i++) {
        float inv = 1.0f / rsum[i];
        #pragma unroll
        for (int j = 0; j < 4; j++)
            O[(q0 + tm + i) * DMODEL + colh + tn + j] = o[i][j] * inv;
    }
}

// ---------------- residual add + layernorm (reference form: /(std+eps)) -------
__global__ void __launch_bounds__(128)
add_ln_kernel(const float* __restrict__ A, const float* __restrict__ Bv,
              const float* __restrict__ gamma, const float* __restrict__ beta,
              float* __restrict__ out)
{
    const int row = blockIdx.x;
    const int tid = threadIdx.x;
    __shared__ float red[4];

    const float4 a4 = reinterpret_cast<const float4*>(A  + (size_t)row * DMODEL)[tid];
    const float4 b4 = reinterpret_cast<const float4*>(Bv + (size_t)row * DMODEL)[tid];
    float x0 = a4.x + b4.x, x1 = a4.y + b4.y, x2 = a4.z + b4.z, x3 = a4.w + b4.w;

    float s = x0 + x1 + x2 + x3;
    #pragma unroll
    for (int off = 16; off; off >>= 1) s += __shfl_xor_sync(0xffffffffu, s, off);
    if ((tid & 31) == 0) red[tid >> 5] = s;
    __syncthreads();
    s = red[0] + red[1] + red[2] + red[3];
    const float mean = s * (1.0f / DMODEL);

    float d0 = x0 - mean, d1 = x1 - mean, d2 = x2 - mean, d3 = x3 - mean;
    float v = d0 * d0 + d1 * d1 + d2 * d2 + d3 * d3;
    #pragma unroll
    for (int off = 16; off; off >>= 1) v += __shfl_xor_sync(0xffffffffu, v, off);
    __syncthreads();                       // protect red[] reuse
    if ((tid & 31) == 0) red[tid >> 5] = v;
    __syncthreads();
    v = (red[0] + red[1] + red[2] + red[3]) * (1.0f / DMODEL);

    const float inv = 1.0f / (sqrtf(v) + EPS);
    const float4 g4  = reinterpret_cast<const float4*>(gamma)[tid];
    const float4 be4 = reinterpret_cast<const float4*>(beta )[tid];
    float4 o4;
    o4.x = d0 * inv * g4.x + be4.x;
    o4.y = d1 * inv * g4.y + be4.y;
    o4.z = d2 * inv * g4.z + be4.z;
    o4.w = d3 * inv * g4.w + be4.w;
    reinterpret_cast<float4*>(out + (size_t)row * DMODEL)[tid] = o4;
}

// ---------------- host launch --------------------------------------------------
extern "C" void kernel_launch(void* const* d_in, const int* in_sizes, int n_in,
                              void* d_out, int out_size)
{
    const float* x   = (const float*)d_in[0];
    const float* Wq  = (const float*)d_in[1];
    const float* bq  = (const float*)d_in[2];
    const float* Wk  = (const float*)d_in[3];
    const float* bk  = (const float*)d_in[4];
    const float* Wv  = (const float*)d_in[5];
    const float* bv  = (const float*)d_in[6];
    const float* Wo  = (const float*)d_in[7];
    const float* bo  = (const float*)d_in[8];
    const float* W1  = (const float*)d_in[9];
    const float* b1  = (const float*)d_in[10];
    const float* W2  = (const float*)d_in[11];
    const float* b2  = (const float*)d_in[12];
    const float* g1  = (const float*)d_in[13];
    const float* be1 = (const float*)d_in[14];
    const float* g2  = (const float*)d_in[15];
    const float* be2 = (const float*)d_in[16];
    float* out = (float*)d_out;

    float *Qp, *Kp, *Vp, *AOp, *X1p, *FFHp;
    cudaGetSymbolAddress((void**)&Qp,   g_Q);
    cudaGetSymbolAddress((void**)&Kp,   g_K);
    cudaGetSymbolAddress((void**)&Vp,   g_V);
    cudaGetSymbolAddress((void**)&AOp,  g_AO);
    cudaGetSymbolAddress((void**)&X1p,  g_X1);
    cudaGetSymbolAddress((void**)&FFHp, g_FFH);

    cudaFuncSetAttribute(attn_kernel, cudaFuncAttributeMaxDynamicSharedMemorySize, ATT_SMEM);

    const dim3 t256(256);
    const dim3 gProj(DMODEL / GBN, ROWS / GBM);   // (8, 128)
    const dim3 gFF1 (DFF    / GBN, ROWS / GBM);   // (32, 128)

    // QKV projections
    gemm_bias_kernel<<<gProj, t256>>>(x, Wq, bq, Qp, ROWS, DMODEL, DMODEL, 0);
    gemm_bias_kernel<<<gProj, t256>>>(x, Wk, bk, Kp, ROWS, DMODEL, DMODEL, 0);
    gemm_bias_kernel<<<gProj, t256>>>(x, Wv, bv, Vp, ROWS, DMODEL, DMODEL, 0);

    // attention (flash, per batch-head)
    attn_kernel<<<dim3(SEQ / 64, BATCH * NHEADS), t256, ATT_SMEM>>>(Qp, Kp, Vp, AOp);

    // output projection (into Qp, now free) + LN1
    gemm_bias_kernel<<<gProj, t256>>>(AOp, Wo, bo, Qp, ROWS, DMODEL, DMODEL, 0);
    add_ln_kernel<<<ROWS, 128>>>(x, Qp, g1, be1, X1p);

    // FFN
    gemm_bias_kernel<<<gFF1,  t256>>>(X1p,  W1, b1, FFHp, ROWS, DFF,    DMODEL, 1);
    gemm_bias_kernel<<<gProj, t256>>>(FFHp, W2, b2, Kp,   ROWS, DMODEL, DFF,    0);

    // LN2 -> final output
    add_ln_kernel<<<ROWS, 128>>>(X1p, Kp, g2, be2, out);
}

// round 4
// speedup vs baseline: 3.7215x; 3.7198x over previous
#include <cuda_runtime.h>
#include <math.h>

#define BATCH   2
#define SEQ     4096
#define DMODEL  512
#define NHEADS  8
#define DK      64
#define DFF     2048
#define ROWS    (BATCH * SEQ)   // 8192
#define EPS     1e-5f

// ---------------- scratch (static device globals; no allocs allowed) ----------
__device__ float g_Q  [ROWS * DMODEL];
__device__ float g_K  [ROWS * DMODEL];
__device__ float g_V  [ROWS * DMODEL];
__device__ float g_AO [ROWS * DMODEL];
__device__ float g_X1 [ROWS * DMODEL];
__device__ float g_FFH[ROWS * DFF];

// ---------------- tf32 helpers ------------------------------------------------
__device__ __forceinline__ float f2tf32(float x) {
    unsigned r;
    asm("cvt.rna.tf32.f32 %0, %1;" : "=r"(r) : "f"(x));
    return __uint_as_float(r);
}

__device__ __forceinline__ void mma_tf32(float* c,
                                         float a0, float a1, float a2, float a3,
                                         float b0, float b1)
{
    asm volatile(
        "mma.sync.aligned.m16n8k8.row.col.f32.tf32.tf32.f32 "
        "{%0,%1,%2,%3}, {%4,%5,%6,%7}, {%8,%9}, {%0,%1,%2,%3};"
        : "+f"(c[0]), "+f"(c[1]), "+f"(c[2]), "+f"(c[3])
        : "r"(__float_as_uint(a0)), "r"(__float_as_uint(a1)),
          "r"(__float_as_uint(a2)), "r"(__float_as_uint(a3)),
          "r"(__float_as_uint(b0)), "r"(__float_as_uint(b1)));
}

// ---------------- tf32 tensor-core GEMM: C = A(MxK)@B(KxN) + bias, opt relu ---
// block tile 128x128x16, 256 threads, warps 2(m) x 4(n), warp tile 64x32
#define TBM 128
#define TBN 128
#define TBK 16
#define ASTR (TBK + 4)    // 20  -> A-frag pattern conflict-free
#define BSTR (TBN + 8)    // 136 -> B-frag pattern conflict-free

__global__ void __launch_bounds__(256)
gemm_tc(const float* __restrict__ A, const float* __restrict__ B,
        const float* __restrict__ bias, float* __restrict__ C,
        int M, int N, int K, int relu)
{
    __shared__ float As[TBM][ASTR];
    __shared__ float Bs[TBK][BSTR];

    const int tid  = threadIdx.x;
    const int warp = tid >> 5, lane = tid & 31;
    const int wm = warp >> 2;          // 0..1
    const int wn = warp & 3;           // 0..3
    const int r    = lane >> 2;        // 0..7
    const int cg   = lane & 3;         // 0..3
    const int row0 = blockIdx.y * TBM;
    const int col0 = blockIdx.x * TBN;

    float acc[4][4][4] = {};           // [mfrag][nfrag][c0..c3]

    for (int k0 = 0; k0 < K; k0 += TBK) {
        __syncthreads();
        // A tile: 128 x 16
        #pragma unroll
        for (int i = 0; i < 2; i++) {
            int l   = tid + i * 256;       // 0..511 float4 slots
            int row = l >> 2;
            int c4  = (l & 3) * 4;
            float4 v = *reinterpret_cast<const float4*>(&A[(size_t)(row0 + row) * K + k0 + c4]);
            float4 w = make_float4(f2tf32(v.x), f2tf32(v.y), f2tf32(v.z), f2tf32(v.w));
            *reinterpret_cast<float4*>(&As[row][c4]) = w;
        }
        // B tile: 16 x 128
        #pragma unroll
        for (int i = 0; i < 2; i++) {
            int l   = tid + i * 256;
            int row = l >> 5;
            int c4  = (l & 31) * 4;
            float4 v = *reinterpret_cast<const float4*>(&B[(size_t)(k0 + row) * N + col0 + c4]);
            float4 w = make_float4(f2tf32(v.x), f2tf32(v.y), f2tf32(v.z), f2tf32(v.w));
            *reinterpret_cast<float4*>(&Bs[row][c4]) = w;
        }
        __syncthreads();

        #pragma unroll
        for (int ks = 0; ks < 2; ks++) {
            const int kk = ks * 8;
            float a[4][4];
            #pragma unroll
            for (int mi = 0; mi < 4; mi++) {
                int mb = wm * 64 + mi * 16;
                a[mi][0] = As[mb + r    ][kk + cg    ];
                a[mi][1] = As[mb + r + 8][kk + cg    ];
                a[mi][2] = As[mb + r    ][kk + cg + 4];
                a[mi][3] = As[mb + r + 8][kk + cg + 4];
            }
            #pragma unroll
            for (int ni = 0; ni < 4; ni++) {
                int nb = wn * 32 + ni * 8;
                float b0 = Bs[kk + cg    ][nb + r];
                float b1 = Bs[kk + cg + 4][nb + r];
                #pragma unroll
                for (int mi = 0; mi < 4; mi++)
                    mma_tf32(acc[mi][ni], a[mi][0], a[mi][1], a[mi][2], a[mi][3], b0, b1);
            }
        }
    }

    // epilogue
    #pragma unroll
    for (int mi = 0; mi < 4; mi++) {
        int mb = row0 + wm * 64 + mi * 16;
        #pragma unroll
        for (int ni = 0; ni < 4; ni++) {
            int col = col0 + wn * 32 + ni * 8 + 2 * cg;
            float bs0 = bias[col], bs1 = bias[col + 1];
            #pragma unroll
            for (int half = 0; half < 2; half++) {
                int row = mb + r + half * 8;
                float v0 = acc[mi][ni][2 * half]     + bs0;
                float v1 = acc[mi][ni][2 * half + 1] + bs1;
                if (relu) { v0 = fmaxf(v0, 0.0f); v1 = fmaxf(v1, 0.0f); }
                *reinterpret_cast<float2*>(&C[(size_t)row * N + col]) = make_float2(v0, v1);
            }
        }
    }
}

// ---------------- flash attention, tf32 tensor cores --------------------------
// grid: (SEQ/64, BATCH*NHEADS); 128 threads (4 warps x 16 query rows)
#define QSTR 68
#define VSTR 72
#define ATT_SMEM ((64 * QSTR + 64 * QSTR + 64 * VSTR + 64 * QSTR) * (int)sizeof(float))

__global__ void __launch_bounds__(128)
attn_tc(const float* __restrict__ Q, const float* __restrict__ K,
        const float* __restrict__ V, float* __restrict__ O)
{
    extern __shared__ float sh[];
    float* Qs = sh;                   // [64][68]
    float* Ks = Qs + 64 * QSTR;       // [64][68]
    float* Vs = Ks + 64 * QSTR;       // [64][72]
    float* Ps = Vs + 64 * VSTR;       // [64][68]

    const int tid  = threadIdx.x;
    const int warp = tid >> 5, lane = tid & 31;
    const int r    = lane >> 2;       // 0..7
    const int cg   = lane & 3;        // 0..3
    const int wb   = warp * 16;       // warp's query-row base within tile

    const int qt = blockIdx.x;
    const int bh = blockIdx.y;
    const int b  = bh >> 3, h = bh & 7;
    const int base = b * SEQ;
    const int q0   = base + qt * 64;
    const int colh = h * DK;

    // load Q tile (scaled by 1/sqrt(dk), rounded to tf32)
    #pragma unroll
    for (int i = 0; i < 8; i++) {
        int l   = tid + i * 128;      // 0..1023 float4 slots
        int row = l >> 4;
        int c4  = (l & 15) * 4;
        float4 v = *reinterpret_cast<const float4*>(&Q[(size_t)(q0 + row) * DMODEL + colh + c4]);
        float4 w = make_float4(f2tf32(0.125f * v.x), f2tf32(0.125f * v.y),
                               f2tf32(0.125f * v.z), f2tf32(0.125f * v.w));
        *reinterpret_cast<float4*>(&Qs[row * QSTR + c4]) = w;
    }

    float o[8][4] = {};
    float rmax[2] = {-1e30f, -1e30f};
    float rsum[2] = {0.0f, 0.0f};

    for (int j0 = 0; j0 < SEQ; j0 += 64) {
        __syncthreads();              // prior PV reads of Ks/Vs/Ps complete
        const int kr = base + j0;
        #pragma unroll
        for (int i = 0; i < 8; i++) {
            int l   = tid + i * 128;
            int row = l >> 4;
            int c4  = (l & 15) * 4;
            float4 kv = *reinterpret_cast<const float4*>(&K[(size_t)(kr + row) * DMODEL + colh + c4]);
            float4 vv = *reinterpret_cast<const float4*>(&V[(size_t)(kr + row) * DMODEL + colh + c4]);
            *reinterpret_cast<float4*>(&Ks[row * QSTR + c4]) =
                make_float4(f2tf32(kv.x), f2tf32(kv.y), f2tf32(kv.z), f2tf32(kv.w));
            *reinterpret_cast<float4*>(&Vs[row * VSTR + c4]) =
                make_float4(f2tf32(vv.x), f2tf32(vv.y), f2tf32(vv.z), f2tf32(vv.w));
        }
        __syncthreads();

        // S = Q @ K^T : per warp m16 x n64 x k64
        float s[8][4] = {};
        #pragma unroll
        for (int kk8 = 0; kk8 < 8; kk8++) {
            const int kk = kk8 * 8;
            float a0 = Qs[(wb + r    ) * QSTR + kk + cg    ];
            float a1 = Qs[(wb + r + 8) * QSTR + kk + cg    ];
            float a2 = Qs[(wb + r    ) * QSTR + kk + cg + 4];
            float a3 = Qs[(wb + r + 8) * QSTR + kk + cg + 4];
            #pragma unroll
            for (int ni = 0; ni < 8; ni++) {
                float b0 = Ks[(ni * 8 + r) * QSTR + kk + cg    ];
                float b1 = Ks[(ni * 8 + r) * QSTR + kk + cg + 4];
                mma_tf32(s[ni], a0, a1, a2, a3, b0, b1);
            }
        }

        // online softmax over the two rows this thread touches (r, r+8)
        #pragma unroll
        for (int z = 0; z < 2; z++) {
            float mx = -1e30f;
            #pragma unroll
            for (int ni = 0; ni < 8; ni++)
                mx = fmaxf(mx, fmaxf(s[ni][2 * z], s[ni][2 * z + 1]));
            mx = fmaxf(mx, __shfl_xor_sync(0xffffffffu, mx, 1));
            mx = fmaxf(mx, __shfl_xor_sync(0xffffffffu, mx, 2));
            float nm   = fmaxf(rmax[z], mx);
            float corr = __expf(rmax[z] - nm);
            rmax[z] = nm;
            float ps = 0.0f;
            #pragma unroll
            for (int ni = 0; ni < 8; ni++) {
                float e0 = __expf(s[ni][2 * z]     - nm);
                float e1 = __expf(s[ni][2 * z + 1] - nm);
                s[ni][2 * z] = e0; s[ni][2 * z + 1] = e1;
                ps += e0 + e1;
            }
            ps += __shfl_xor_sync(0xffffffffu, ps, 1);
            ps += __shfl_xor_sync(0xffffffffu, ps, 2);
            rsum[z] = rsum[z] * corr + ps;
            #pragma unroll
            for (int ni = 0; ni < 8; ni++) {
                o[ni][2 * z]     *= corr;
                o[ni][2 * z + 1] *= corr;
            }
        }

        // write P (tf32) to smem
        #pragma unroll
        for (int ni = 0; ni < 8; ni++) {
            int col = ni * 8 + 2 * cg;
            #pragma unroll
            for (int z = 0; z < 2; z++) {
                int row = wb + r + z * 8;
                *reinterpret_cast<float2*>(&Ps[row * QSTR + col]) =
                    make_float2(f2tf32(s[ni][2 * z]), f2tf32(s[ni][2 * z + 1]));
            }
        }
        __syncthreads();

        // O += P @ V : per warp m16 x n64 x k64
        #pragma unroll
        for (int kk8 = 0; kk8 < 8; kk8++) {
            const int kk = kk8 * 8;
            float a0 = Ps[(wb + r    ) * QSTR + kk + cg    ];
            float a1 = Ps[(wb + r + 8) * QSTR + kk + cg    ];
            float a2 = Ps[(wb + r    ) * QSTR + kk + cg + 4];
            float a3 = Ps[(wb + r + 8) * QSTR + kk + cg + 4];
            #pragma unroll
            for (int ni = 0; ni < 8; ni++) {
                float b0 = Vs[(kk + cg    ) * VSTR + ni * 8 + r];
                float b1 = Vs[(kk + cg + 4) * VSTR + ni * 8 + r];
                mma_tf32(o[ni], a0, a1, a2, a3, b0, b1);
            }
        }
    }

    // epilogue: normalize and store
    #pragma unroll
    for (int z = 0; z < 2; z++) {
        float inv = 1.0f / rsum[z];
        int row = q0 + wb + r + z * 8;
        #pragma unroll
        for (int ni = 0; ni < 8; ni++) {
            int col = colh + ni * 8 + 2 * cg;
            *reinterpret_cast<float2*>(&O[(size_t)row * DMODEL + col]) =
                make_float2(o[ni][2 * z] * inv, o[ni][2 * z + 1] * inv);
        }
    }
}

// ---------------- residual add + layernorm (reference form: /(std+eps)) -------
__global__ void __launch_bounds__(128)
add_ln_kernel(const float* __restrict__ A, const float* __restrict__ Bv,
              const float* __restrict__ gamma, const float* __restrict__ beta,
              float* __restrict__ out)
{
    const int row = blockIdx.x;
    const int tid = threadIdx.x;
    __shared__ float red[4];

    const float4 a4 = reinterpret_cast<const float4*>(A  + (size_t)row * DMODEL)[tid];
    const float4 b4 = reinterpret_cast<const float4*>(Bv + (size_t)row * DMODEL)[tid];
    float x0 = a4.x + b4.x, x1 = a4.y + b4.y, x2 = a4.z + b4.z, x3 = a4.w + b4.w;

    float s = x0 + x1 + x2 + x3;
    #pragma unroll
    for (int off = 16; off; off >>= 1) s += __shfl_xor_sync(0xffffffffu, s, off);
    if ((tid & 31) == 0) red[tid >> 5] = s;
    __syncthreads();
    s = red[0] + red[1] + red[2] + red[3];
    const float mean = s * (1.0f / DMODEL);

    float d0 = x0 - mean, d1 = x1 - mean, d2 = x2 - mean, d3 = x3 - mean;
    float v = d0 * d0 + d1 * d1 + d2 * d2 + d3 * d3;
    #pragma unroll
    for (int off = 16; off; off >>= 1) v += __shfl_xor_sync(0xffffffffu, v, off);
    __syncthreads();
    if ((tid & 31) == 0) red[tid >> 5] = v;
    __syncthreads();
    v = (red[0] + red[1] + red[2] + red[3]) * (1.0f / DMODEL);

    const float inv = 1.0f / (sqrtf(v) + EPS);
    const float4 g4  = reinterpret_cast<const float4*>(gamma)[tid];
    const float4 be4 = reinterpret_cast<const float4*>(beta )[tid];
    float4 o4;
    o4.x = d0 * inv * g4.x + be4.x;
    o4.y = d1 * inv * g4.y + be4.y;
    o4.z = d2 * inv * g4.z + be4.z;
    o4.w = d3 * inv * g4.w + be4.w;
    reinterpret_cast<float4*>(out + (size_t)row * DMODEL)[tid] = o4;
}

// ---------------- host launch --------------------------------------------------
extern "C" void kernel_launch(void* const* d_in, const int* in_sizes, int n_in,
                              void* d_out, int out_size)
{
    const float* x   = (const float*)d_in[0];
    const float* Wq  = (const float*)d_in[1];
    const float* bq  = (const float*)d_in[2];
    const float* Wk  = (const float*)d_in[3];
    const float* bk  = (const float*)d_in[4];
    const float* Wv  = (const float*)d_in[5];
    const float* bv  = (const float*)d_in[6];
    const float* Wo  = (const float*)d_in[7];
    const float* bo  = (const float*)d_in[8];
    const float* W1  = (const float*)d_in[9];
    const float* b1  = (const float*)d_in[10];
    const float* W2  = (const float*)d_in[11];
    const float* b2  = (const float*)d_in[12];
    const float* g1  = (const float*)d_in[13];
    const float* be1 = (const float*)d_in[14];
    const float* g2  = (const float*)d_in[15];
    const float* be2 = (const float*)d_in[16];
    float* out = (float*)d_out;

    float *Qp, *Kp, *Vp, *AOp, *X1p, *FFHp;
    cudaGetSymbolAddress((void**)&Qp,   g_Q);
    cudaGetSymbolAddress((void**)&Kp,   g_K);
    cudaGetSymbolAddress((void**)&Vp,   g_V);
    cudaGetSymbolAddress((void**)&AOp,  g_AO);
    cudaGetSymbolAddress((void**)&X1p,  g_X1);
    cudaGetSymbolAddress((void**)&FFHp, g_FFH);

    cudaFuncSetAttribute(attn_tc, cudaFuncAttributeMaxDynamicSharedMemorySize, ATT_SMEM);

    const dim3 t256(256), t128(128);
    const dim3 gProj(DMODEL / TBN, ROWS / TBM);   // (4, 64)
    const dim3 gFF1 (DFF    / TBN, ROWS / TBM);   // (16, 64)

    // QKV projections
    gemm_tc<<<gProj, t256>>>(x, Wq, bq, Qp, ROWS, DMODEL, DMODEL, 0);
    gemm_tc<<<gProj, t256>>>(x, Wk, bk, Kp, ROWS, DMODEL, DMODEL, 0);
    gemm_tc<<<gProj, t256>>>(x, Wv, bv, Vp, ROWS, DMODEL, DMODEL, 0);

    // attention
    attn_tc<<<dim3(SEQ / 64, BATCH * NHEADS), t128, ATT_SMEM>>>(Qp, Kp, Vp, AOp);

    // output projection + LN1
    gemm_tc<<<gProj, t256>>>(AOp, Wo, bo, Qp, ROWS, DMODEL, DMODEL, 0);
    add_ln_kernel<<<ROWS, 128>>>(x, Qp, g1, be1, X1p);

    // FFN
    gemm_tc<<<gFF1,  t256>>>(X1p,  W1, b1, FFHp, ROWS, DFF,    DMODEL, 1);
    gemm_tc<<<gProj, t256>>>(FFHp, W2, b2, Kp,   ROWS, DMODEL, DFF,    0);

    // LN2 -> final output
    add_ln_kernel<<<ROWS, 128>>>(X1p, Kp, g2, be2, out);
}

// round 5
// speedup vs baseline: 3.9464x; 1.0604x over previous
#include <cuda_runtime.h>
#include <math.h>

#define BATCH   2
#define SEQ     4096
#define DMODEL  512
#define NHEADS  8
#define DK      64
#define DFF     2048
#define ROWS    (BATCH * SEQ)   // 8192
#define EPS     1e-5f

// ---------------- scratch (static device globals; no allocs allowed) ----------
__device__ float g_Q  [ROWS * DMODEL];
__device__ float g_K  [ROWS * DMODEL];
__device__ float g_V  [ROWS * DMODEL];
__device__ float g_AO [ROWS * DMODEL];
__device__ float g_X1 [ROWS * DMODEL];
__device__ float g_FFH[ROWS * DFF];

// ---------------- tf32 helpers ------------------------------------------------
__device__ __forceinline__ float f2tf32(float x) {
    unsigned r;
    asm("cvt.rna.tf32.f32 %0, %1;" : "=r"(r) : "f"(x));
    return __uint_as_float(r);
}

__device__ __forceinline__ void mma_tf32(float* c,
                                         float a0, float a1, float a2, float a3,
                                         float b0, float b1)
{
    asm volatile(
        "mma.sync.aligned.m16n8k8.row.col.f32.tf32.tf32.f32 "
        "{%0,%1,%2,%3}, {%4,%5,%6,%7}, {%8,%9}, {%0,%1,%2,%3};"
        : "+f"(c[0]), "+f"(c[1]), "+f"(c[2]), "+f"(c[3])
        : "r"(__float_as_uint(a0)), "r"(__float_as_uint(a1)),
          "r"(__float_as_uint(a2)), "r"(__float_as_uint(a3)),
          "r"(__float_as_uint(b0)), "r"(__float_as_uint(b1)));
}

// ---------------- tf32 tensor-core GEMM: C = A(MxK)@B(KxN) + bias, opt relu ---
// block tile 128x128x16, 256 threads, warps 2(m) x 4(n), warp tile 64x32
#define TBM 128
#define TBN 128
#define TBK 16
#define ASTR (TBK + 4)    // 20  -> A-frag pattern conflict-free
#define BSTR (TBN + 8)    // 136 -> B-frag pattern conflict-free

__global__ void __launch_bounds__(256)
gemm_tc(const float* __restrict__ A, const float* __restrict__ B,
        const float* __restrict__ bias, float* __restrict__ C,
        int M, int N, int K, int relu)
{
    __shared__ float As[TBM][ASTR];
    __shared__ float Bs[TBK][BSTR];

    const int tid  = threadIdx.x;
    const int warp = tid >> 5, lane = tid & 31;
    const int wm = warp >> 2;          // 0..1
    const int wn = warp & 3;           // 0..3
    const int r    = lane >> 2;        // 0..7
    const int cg   = lane & 3;         // 0..3
    const int row0 = blockIdx.y * TBM;
    const int col0 = blockIdx.x * TBN;

    float acc[4][4][4] = {};           // [mfrag][nfrag][c0..c3]

    for (int k0 = 0; k0 < K; k0 += TBK) {
        __syncthreads();
        // A tile: 128 x 16
        #pragma unroll
        for (int i = 0; i < 2; i++) {
            int l   = tid + i * 256;       // 0..511 float4 slots
            int row = l >> 2;
            int c4  = (l & 3) * 4;
            float4 v = *reinterpret_cast<const float4*>(&A[(size_t)(row0 + row) * K + k0 + c4]);
            float4 w = make_float4(f2tf32(v.x), f2tf32(v.y), f2tf32(v.z), f2tf32(v.w));
            *reinterpret_cast<float4*>(&As[row][c4]) = w;
        }
        // B tile: 16 x 128
        #pragma unroll
        for (int i = 0; i < 2; i++) {
            int l   = tid + i * 256;
            int row = l >> 5;
            int c4  = (l & 31) * 4;
            float4 v = *reinterpret_cast<const float4*>(&B[(size_t)(k0 + row) * N + col0 + c4]);
            float4 w = make_float4(f2tf32(v.x), f2tf32(v.y), f2tf32(v.z), f2tf32(v.w));
            *reinterpret_cast<float4*>(&Bs[row][c4]) = w;
        }
        __syncthreads();

        #pragma unroll
        for (int ks = 0; ks < 2; ks++) {
            const int kk = ks * 8;
            float a[4][4];
            #pragma unroll
            for (int mi = 0; mi < 4; mi++) {
                int mb = wm * 64 + mi * 16;
                a[mi][0] = As[mb + r    ][kk + cg    ];
                a[mi][1] = As[mb + r + 8][kk + cg    ];
                a[mi][2] = As[mb + r    ][kk + cg + 4];
                a[mi][3] = As[mb + r + 8][kk + cg + 4];
            }
            #pragma unroll
            for (int ni = 0; ni < 4; ni++) {
                int nb = wn * 32 + ni * 8;
                float b0 = Bs[kk + cg    ][nb + r];
                float b1 = Bs[kk + cg + 4][nb + r];
                #pragma unroll
                for (int mi = 0; mi < 4; mi++)
                    mma_tf32(acc[mi][ni], a[mi][0], a[mi][1], a[mi][2], a[mi][3], b0, b1);
            }
        }
    }

    // epilogue
    #pragma unroll
    for (int mi = 0; mi < 4; mi++) {
        int mb = row0 + wm * 64 + mi * 16;
        #pragma unroll
        for (int ni = 0; ni < 4; ni++) {
            int col = col0 + wn * 32 + ni * 8 + 2 * cg;
            float bs0 = bias[col], bs1 = bias[col + 1];
            #pragma unroll
            for (int half = 0; half < 2; half++) {
                int row = mb + r + half * 8;
                float v0 = acc[mi][ni][2 * half]     + bs0;
                float v1 = acc[mi][ni][2 * half + 1] + bs1;
                if (relu) { v0 = fmaxf(v0, 0.0f); v1 = fmaxf(v1, 0.0f); }
                *reinterpret_cast<float2*>(&C[(size_t)row * N + col]) = make_float2(v0, v1);
            }
        }
    }
}

// ---------------- flash attention, tf32 tensor cores, m32 warp tiles ----------
// grid: (SEQ/128, BATCH*NHEADS); 128 threads = 4 warps x 32 query rows each
#define QTILE 128
#define QSTR 68
#define VSTR 72
#define ATT_SMEM ((QTILE * QSTR + 64 * QSTR + 64 * VSTR + QTILE * QSTR) * (int)sizeof(float))

__global__ void __launch_bounds__(128)
attn_tc(const float* __restrict__ Q, const float* __restrict__ K,
        const float* __restrict__ V, float* __restrict__ O)
{
    extern __shared__ float sh[];
    float* Qs = sh;                      // [128][68]
    float* Ks = Qs + QTILE * QSTR;       // [64][68]
    float* Vs = Ks + 64 * QSTR;          // [64][72]
    float* Ps = Vs + 64 * VSTR;          // [128][68]

    const int tid  = threadIdx.x;
    const int warp = tid >> 5, lane = tid & 31;
    const int r    = lane >> 2;          // 0..7
    const int cg   = lane & 3;           // 0..3
    const int wb   = warp * 32;          // warp's query-row base (m32 per warp)

    const int qt = blockIdx.x;
    const int bh = blockIdx.y;
    const int b  = bh >> 3, h = bh & 7;
    const int base = b * SEQ;
    const int q0   = base + qt * QTILE;
    const int colh = h * DK;

    // load Q tile (128 rows, scaled by 1/sqrt(dk), rounded to tf32)
    #pragma unroll
    for (int i = 0; i < 16; i++) {
        int l   = tid + i * 128;         // 0..2047 float4 slots
        int row = l >> 4;
        int c4  = (l & 15) * 4;
        float4 v = *reinterpret_cast<const float4*>(&Q[(size_t)(q0 + row) * DMODEL + colh + c4]);
        float4 w = make_float4(f2tf32(0.125f * v.x), f2tf32(0.125f * v.y),
                               f2tf32(0.125f * v.z), f2tf32(0.125f * v.w));
        *reinterpret_cast<float4*>(&Qs[row * QSTR + c4]) = w;
    }

    float o[2][8][4] = {};
    float rmax[2][2], rsum[2][2];
    #pragma unroll
    for (int mf = 0; mf < 2; mf++)
        #pragma unroll
        for (int z = 0; z < 2; z++) { rmax[mf][z] = -1e30f; rsum[mf][z] = 0.0f; }

    for (int j0 = 0; j0 < SEQ; j0 += 64) {
        __syncthreads();                 // prior PV reads of Ks/Vs/Ps complete
        const int kr = base + j0;
        #pragma unroll
        for (int i = 0; i < 8; i++) {
            int l   = tid + i * 128;     // 0..1023 float4 slots (64 rows)
            int row = l >> 4;
            int c4  = (l & 15) * 4;
            float4 kv = *reinterpret_cast<const float4*>(&K[(size_t)(kr + row) * DMODEL + colh + c4]);
            float4 vv = *reinterpret_cast<const float4*>(&V[(size_t)(kr + row) * DMODEL + colh + c4]);
            *reinterpret_cast<float4*>(&Ks[row * QSTR + c4]) =
                make_float4(f2tf32(kv.x), f2tf32(kv.y), f2tf32(kv.z), f2tf32(kv.w));
            *reinterpret_cast<float4*>(&Vs[row * VSTR + c4]) =
                make_float4(f2tf32(vv.x), f2tf32(vv.y), f2tf32(vv.z), f2tf32(vv.w));
        }
        __syncthreads();

        // S = Q @ K^T : per warp m32 x n64 x k64 (B-frags shared across 2 m-frags)
        float s[2][8][4] = {};
        #pragma unroll
        for (int kk8 = 0; kk8 < 8; kk8++) {
            const int kk = kk8 * 8;
            float a[2][4];
            #pragma unroll
            for (int mf = 0; mf < 2; mf++) {
                int mb = wb + mf * 16;
                a[mf][0] = Qs[(mb + r    ) * QSTR + kk + cg    ];
                a[mf][1] = Qs[(mb + r + 8) * QSTR + kk + cg    ];
                a[mf][2] = Qs[(mb + r    ) * QSTR + kk + cg + 4];
                a[mf][3] = Qs[(mb + r + 8) * QSTR + kk + cg + 4];
            }
            #pragma unroll
            for (int ni = 0; ni < 8; ni++) {
                float b0 = Ks[(ni * 8 + r) * QSTR + kk + cg    ];
                float b1 = Ks[(ni * 8 + r) * QSTR + kk + cg + 4];
                mma_tf32(s[0][ni], a[0][0], a[0][1], a[0][2], a[0][3], b0, b1);
                mma_tf32(s[1][ni], a[1][0], a[1][1], a[1][2], a[1][3], b0, b1);
            }
        }

        // online softmax (per m-frag, per row-half)
        #pragma unroll
        for (int mf = 0; mf < 2; mf++) {
            #pragma unroll
            for (int z = 0; z < 2; z++) {
                float mx = -1e30f;
                #pragma unroll
                for (int ni = 0; ni < 8; ni++)
                    mx = fmaxf(mx, fmaxf(s[mf][ni][2 * z], s[mf][ni][2 * z + 1]));
                mx = fmaxf(mx, __shfl_xor_sync(0xffffffffu, mx, 1));
                mx = fmaxf(mx, __shfl_xor_sync(0xffffffffu, mx, 2));
                float nm   = fmaxf(rmax[mf][z], mx);
                float corr = __expf(rmax[mf][z] - nm);
                rmax[mf][z] = nm;
                float ps = 0.0f;
                #pragma unroll
                for (int ni = 0; ni < 8; ni++) {
                    float e0 = __expf(s[mf][ni][2 * z]     - nm);
                    float e1 = __expf(s[mf][ni][2 * z + 1] - nm);
                    s[mf][ni][2 * z] = e0; s[mf][ni][2 * z + 1] = e1;
                    ps += e0 + e1;
                }
                ps += __shfl_xor_sync(0xffffffffu, ps, 1);
                ps += __shfl_xor_sync(0xffffffffu, ps, 2);
                rsum[mf][z] = rsum[mf][z] * corr + ps;
                #pragma unroll
                for (int ni = 0; ni < 8; ni++) {
                    o[mf][ni][2 * z]     *= corr;
                    o[mf][ni][2 * z + 1] *= corr;
                }
            }
        }

        // write P (tf32) to smem
        #pragma unroll
        for (int mf = 0; mf < 2; mf++) {
            #pragma unroll
            for (int ni = 0; ni < 8; ni++) {
                int col = ni * 8 + 2 * cg;
                #pragma unroll
                for (int z = 0; z < 2; z++) {
                    int row = wb + mf * 16 + r + z * 8;
                    *reinterpret_cast<float2*>(&Ps[row * QSTR + col]) =
                        make_float2(f2tf32(s[mf][ni][2 * z]), f2tf32(s[mf][ni][2 * z + 1]));
                }
            }
        }
        __syncwarp();   // P written/read within the same warp's rows only

        // O += P @ V : per warp m32 x n64 x k64
        #pragma unroll
        for (int kk8 = 0; kk8 < 8; kk8++) {
            const int kk = kk8 * 8;
            float a[2][4];
            #pragma unroll
            for (int mf = 0; mf < 2; mf++) {
                int mb = wb + mf * 16;
                a[mf][0] = Ps[(mb + r    ) * QSTR + kk + cg    ];
                a[mf][1] = Ps[(mb + r + 8) * QSTR + kk + cg    ];
                a[mf][2] = Ps[(mb + r    ) * QSTR + kk + cg + 4];
                a[mf][3] = Ps[(mb + r + 8) * QSTR + kk + cg + 4];
            }
            #pragma unroll
            for (int ni = 0; ni < 8; ni++) {
                float b0 = Vs[(kk + cg    ) * VSTR + ni * 8 + r];
                float b1 = Vs[(kk + cg + 4) * VSTR + ni * 8 + r];
                mma_tf32(o[0][ni], a[0][0], a[0][1], a[0][2], a[0][3], b0, b1);
                mma_tf32(o[1][ni], a[1][0], a[1][1], a[1][2], a[1][3], b0, b1);
            }
        }
    }

    // epilogue: normalize and store
    #pragma unroll
    for (int mf = 0; mf < 2; mf++) {
        #pragma unroll
        for (int z = 0; z < 2; z++) {
            float inv = 1.0f / rsum[mf][z];
            int row = q0 + wb + mf * 16 + r + z * 8;
            #pragma unroll
            for (int ni = 0; ni < 8; ni++) {
                int col = colh + ni * 8 + 2 * cg;
                *reinterpret_cast<float2*>(&O[(size_t)row * DMODEL + col]) =
                    make_float2(o[mf][ni][2 * z] * inv, o[mf][ni][2 * z + 1] * inv);
            }
        }
    }
}

// ---------------- residual add + layernorm (reference form: /(std+eps)) -------
__global__ void __launch_bounds__(128)
add_ln_kernel(const float* __restrict__ A, const float* __restrict__ Bv,
              const float* __restrict__ gamma, const float* __restrict__ beta,
              float* __restrict__ out)
{
    const int row = blockIdx.x;
    const int tid = threadIdx.x;
    __shared__ float red[4];

    const float4 a4 = reinterpret_cast<const float4*>(A  + (size_t)row * DMODEL)[tid];
    const float4 b4 = reinterpret_cast<const float4*>(Bv + (size_t)row * DMODEL)[tid];
    float x0 = a4.x + b4.x, x1 = a4.y + b4.y, x2 = a4.z + b4.z, x3 = a4.w + b4.w;

    float s = x0 + x1 + x2 + x3;
    #pragma unroll
    for (int off = 16; off; off >>= 1) s += __shfl_xor_sync(0xffffffffu, s, off);
    if ((tid & 31) == 0) red[tid >> 5] = s;
    __syncthreads();
    s = red[0] + red[1] + red[2] + red[3];
    const float mean = s * (1.0f / DMODEL);

    float d0 = x0 - mean, d1 = x1 - mean, d2 = x2 - mean, d3 = x3 - mean;
    float v = d0 * d0 + d1 * d1 + d2 * d2 + d3 * d3;
    #pragma unroll
    for (int off = 16; off; off >>= 1) v += __shfl_xor_sync(0xffffffffu, v, off);
    __syncthreads();
    if ((tid & 31) == 0) red[tid >> 5] = v;
    __syncthreads();
    v = (red[0] + red[1] + red[2] + red[3]) * (1.0f / DMODEL);

    const float inv = 1.0f / (sqrtf(v) + EPS);
    const float4 g4  = reinterpret_cast<const float4*>(gamma)[tid];
    const float4 be4 = reinterpret_cast<const float4*>(beta )[tid];
    float4 o4;
    o4.x = d0 * inv * g4.x + be4.x;
    o4.y = d1 * inv * g4.y + be4.y;
    o4.z = d2 * inv * g4.z + be4.z;
    o4.w = d3 * inv * g4.w + be4.w;
    reinterpret_cast<float4*>(out + (size_t)row * DMODEL)[tid] = o4;
}

// ---------------- host launch --------------------------------------------------
extern "C" void kernel_launch(void* const* d_in, const int* in_sizes, int n_in,
                              void* d_out, int out_size)
{
    const float* x   = (const float*)d_in[0];
    const float* Wq  = (const float*)d_in[1];
    const float* bq  = (const float*)d_in[2];
    const float* Wk  = (const float*)d_in[3];
    const float* bk  = (const float*)d_in[4];
    const float* Wv  = (const float*)d_in[5];
    const float* bv  = (const float*)d_in[6];
    const float* Wo  = (const float*)d_in[7];
    const float* bo  = (const float*)d_in[8];
    const float* W1  = (const float*)d_in[9];
    const float* b1  = (const float*)d_in[10];
    const float* W2  = (const float*)d_in[11];
    const float* b2  = (const float*)d_in[12];
    const float* g1  = (const float*)d_in[13];
    const float* be1 = (const float*)d_in[14];
    const float* g2  = (const float*)d_in[15];
    const float* be2 = (const float*)d_in[16];
    float* out = (float*)d_out;

    float *Qp, *Kp, *Vp, *AOp, *X1p, *FFHp;
    cudaGetSymbolAddress((void**)&Qp,   g_Q);
    cudaGetSymbolAddress((void**)&Kp,   g_K);
    cudaGetSymbolAddress((void**)&Vp,   g_V);
    cudaGetSymbolAddress((void**)&AOp,  g_AO);
    cudaGetSymbolAddress((void**)&X1p,  g_X1);
    cudaGetSymbolAddress((void**)&FFHp, g_FFH);

    cudaFuncSetAttribute(attn_tc, cudaFuncAttributeMaxDynamicSharedMemorySize, ATT_SMEM);

    const dim3 t256(256), t128(128);
    const dim3 gProj(DMODEL / TBN, ROWS / TBM);   // (4, 64)
    const dim3 gFF1 (DFF    / TBN, ROWS / TBM);   // (16, 64)

    // QKV projections
    gemm_tc<<<gProj, t256>>>(x, Wq, bq, Qp, ROWS, DMODEL, DMODEL, 0);
    gemm_tc<<<gProj, t256>>>(x, Wk, bk, Kp, ROWS, DMODEL, DMODEL, 0);
    gemm_tc<<<gProj, t256>>>(x, Wv, bv, Vp, ROWS, DMODEL, DMODEL, 0);

    // attention
    attn_tc<<<dim3(SEQ / QTILE, BATCH * NHEADS), t128, ATT_SMEM>>>(Qp, Kp, Vp, AOp);

    // output projection + LN1
    gemm_tc<<<gProj, t256>>>(AOp, Wo, bo, Qp, ROWS, DMODEL, DMODEL, 0);
    add_ln_kernel<<<ROWS, 128>>>(x, Qp, g1, be1, X1p);

    // FFN
    gemm_tc<<<gFF1,  t256>>>(X1p,  W1, b1, FFHp, ROWS, DFF,    DMODEL, 1);
    gemm_tc<<<gProj, t256>>>(FFHp, W2, b2, Kp,   ROWS, DMODEL, DFF,    0);

    // LN2 -> final output
    add_ln_kernel<<<ROWS, 128>>>(X1p, Kp, g2, be2, out);
}